// round 3
// baseline (speedup 1.0000x reference)
#include <cuda_runtime.h>
#include <math.h>

#define BB 2
#define SS 2048
#define DM 1024
#define NH 16
#define DK 64
#define WIN 512

// Scratch (no cudaMalloc allowed): qkv = 2*2048*3072 f32 (48MB), attn out = 16MB
__device__ float g_qkv[BB * SS * 3 * DM];
__device__ float g_att[BB * SS * DM];

// ---------------------------------------------------------------------------
// SGEMM: C[M,N] = A[M,K] @ B[K,N], row-major, fp32.
// 128x128 block tile, K-step 8, 256 threads, 8x8 register tile per thread.
// Assumes M%128==0, N%128==0, K%8==0 (true for all three calls).
// ---------------------------------------------------------------------------
__global__ __launch_bounds__(256) void sgemm_kernel(
    const float* __restrict__ A, const float* __restrict__ B,
    float* __restrict__ C, int M, int N, int K)
{
    __shared__ float As[8][128];
    __shared__ float Bs[8][128];

    const int tid = threadIdx.x;
    const int tx = tid & 15;        // 0..15 -> 8 columns each
    const int ty = tid >> 4;        // 0..15 -> 8 rows each
    const int m0 = blockIdx.y * 128;
    const int n0 = blockIdx.x * 128;

    float acc[8][8];
#pragma unroll
    for (int i = 0; i < 8; i++)
#pragma unroll
        for (int j = 0; j < 8; j++) acc[i][j] = 0.f;

    const int arow = tid >> 1;            // 0..127
    const int acol = (tid & 1) * 4;       // 0 or 4
    const int brow = tid >> 5;            // 0..7
    const int bcol = (tid & 31) * 4;      // 0..124

    for (int k0 = 0; k0 < K; k0 += 8) {
        float4 av = *(const float4*)(A + (size_t)(m0 + arow) * K + k0 + acol);
        As[acol + 0][arow] = av.x;
        As[acol + 1][arow] = av.y;
        As[acol + 2][arow] = av.z;
        As[acol + 3][arow] = av.w;
        float4 bv = *(const float4*)(B + (size_t)(k0 + brow) * N + n0 + bcol);
        *(float4*)&Bs[brow][bcol] = bv;
        __syncthreads();

#pragma unroll
        for (int kk = 0; kk < 8; kk++) {
            float a[8], b[8];
#pragma unroll
            for (int i = 0; i < 4; i++) {
                ((float4*)a)[0] = *(const float4*)&As[kk][ty * 8];
                ((float4*)a)[1] = *(const float4*)&As[kk][ty * 8 + 4];
                ((float4*)b)[0] = *(const float4*)&Bs[kk][tx * 8];
                ((float4*)b)[1] = *(const float4*)&Bs[kk][tx * 8 + 4];
                break;  // single vector load pair (loop form keeps unroll pragma legal)
            }
#pragma unroll
            for (int i = 0; i < 8; i++)
#pragma unroll
                for (int j = 0; j < 8; j++) acc[i][j] += a[i] * b[j];
        }
        __syncthreads();
    }

#pragma unroll
    for (int i = 0; i < 8; i++) {
        int m = m0 + ty * 8 + i;
        float4* cp = (float4*)(C + (size_t)m * N + n0 + tx * 8);
        cp[0] = make_float4(acc[i][0], acc[i][1], acc[i][2], acc[i][3]);
        cp[1] = make_float4(acc[i][4], acc[i][5], acc[i][6], acc[i][7]);
    }
}

// ---------------------------------------------------------------------------
// RoPE applied in-place to the Q and K slices of g_qkv.
// One thread per (b,s,h,pair). pair i rotates dims (2i, 2i+1), freq i/32.
// ---------------------------------------------------------------------------
__global__ void rope_kernel(float* __restrict__ qkv)
{
    int idx = blockIdx.x * blockDim.x + threadIdx.x;
    if (idx >= BB * SS * NH * (DK / 2)) return;
    int i = idx & 31;
    int h = (idx >> 5) & (NH - 1);
    int s = (idx >> 9) & (SS - 1);
    int b = idx >> 20;

    // inv_freq = 10000^(-i/32); double for exactness, then the fp32 product
    // s*invf matches the reference's fp32 angle to ~1 ulp.
    float invf = (float)exp(-(double)i / 32.0 * log(10000.0));
    float ang = (float)s * invf;
    float sn, cs;
    sincosf(ang, &sn, &cs);

    size_t base = ((size_t)(b * SS + s)) * (3 * DM) + h * DK + 2 * i;
    float qe = qkv[base], qo = qkv[base + 1];
    qkv[base]     = qe * cs - qo * sn;
    qkv[base + 1] = qo * cs + qe * sn;
    float ke = qkv[base + DM], ko = qkv[base + DM + 1];
    qkv[base + DM]     = ke * cs - ko * sn;
    qkv[base + DM + 1] = ko * cs + ke * sn;
}

// ---------------------------------------------------------------------------
// Sliding-window attention: one block per (b,h,q), 128 threads.
// Phase 1: scores (strided keys/thread, float4 K loads)
// Phase 2: block softmax (max + sum reductions)
// Phase 3: P@V with 2 key-phases x 64 dims, coalesced V loads
// ---------------------------------------------------------------------------
__global__ __launch_bounds__(128) void attn_kernel(
    const float* __restrict__ qkv, float* __restrict__ out)
{
    const int q = blockIdx.x & (SS - 1);
    const int h = (blockIdx.x >> 11) & (NH - 1);
    const int b = blockIdx.x >> 15;
    const int t = threadIdx.x;

    __shared__ float qv[DK];
    __shared__ float sc[WIN + 1];
    __shared__ float red[128];

    const size_t row_q = ((size_t)(b * SS + q)) * (3 * DM) + h * DK;
    if (t < DK) qv[t] = qkv[row_q + t];
    __syncthreads();

    int j0 = q - WIN;
    if (j0 < 0) j0 = 0;
    const int nk = q - j0 + 1;   // 1..513

    // Phase 1: scores
    float lmax = -1e30f;
    for (int jj = t; jj < nk; jj += 128) {
        const float* kp = qkv + ((size_t)(b * SS + j0 + jj)) * (3 * DM) + DM + h * DK;
        float dot = 0.f;
#pragma unroll
        for (int d = 0; d < DK; d += 4) {
            float4 k4 = *(const float4*)(kp + d);
            dot += qv[d] * k4.x + qv[d + 1] * k4.y + qv[d + 2] * k4.z + qv[d + 3] * k4.w;
        }
        dot *= 0.125f;            // 1/sqrt(64)
        sc[jj] = dot;
        lmax = fmaxf(lmax, dot);
    }

    // Phase 2a: block max
    red[t] = lmax;
    __syncthreads();
#pragma unroll
    for (int s2 = 64; s2 > 0; s2 >>= 1) {
        if (t < s2) red[t] = fmaxf(red[t], red[t + s2]);
        __syncthreads();
    }
    const float mx = red[0];
    __syncthreads();

    // Phase 2b: exp + block sum
    float lsum = 0.f;
    for (int jj = t; jj < nk; jj += 128) {
        float e = expf(sc[jj] - mx);
        sc[jj] = e;
        lsum += e;
    }
    red[t] = lsum;
    __syncthreads();
#pragma unroll
    for (int s2 = 64; s2 > 0; s2 >>= 1) {
        if (t < s2) red[t] += red[t + s2];
        __syncthreads();
    }
    const float inv = 1.f / red[0];
    __syncthreads();

    // Phase 3: P @ V  (thread t handles dim t&63, key phase t>>6)
    const int d = t & 63;
    float acc = 0.f;
    for (int jj = (t >> 6); jj < nk; jj += 2) {
        const float* vp = qkv + ((size_t)(b * SS + j0 + jj)) * (3 * DM) + 2 * DM + h * DK;
        acc += sc[jj] * vp[d];
    }
    red[t] = acc;
    __syncthreads();
    if (t < 64) {
        out[((size_t)(b * SS + q)) * DM + h * DK + t] = (red[t] + red[t + 64]) * inv;
    }
}

// ---------------------------------------------------------------------------
extern "C" void kernel_launch(void* const* d_in, const int* in_sizes, int n_in,
                              void* d_out, int out_size)
{
    const float* x     = (const float*)d_in[0];   // [2,2048,1024]
    const float* w_qkv = (const float*)d_in[1];   // [1024,3072]
    const float* w_o   = (const float*)d_in[2];   // [1024,1024]
    float* out = (float*)d_out;                   // [2,2048,1024]

    float* qkv = nullptr;
    float* att = nullptr;
    cudaGetSymbolAddress((void**)&qkv, g_qkv);
    cudaGetSymbolAddress((void**)&att, g_att);

    const int M = BB * SS;  // 4096

    // 1) QKV projection: [4096,1024] @ [1024,3072]
    {
        dim3 grid(3 * DM / 128, M / 128);
        sgemm_kernel<<<grid, 256>>>(x, w_qkv, qkv, M, 3 * DM, DM);
    }
    // 2) RoPE on Q and K slices (in place)
    {
        int total = BB * SS * NH * (DK / 2);
        rope_kernel<<<(total + 255) / 256, 256>>>(qkv);
    }
    // 3) Sliding-window attention
    {
        attn_kernel<<<BB * NH * SS, 128>>>(qkv, att);
    }
    // 4) Output projection: [4096,1024] @ [1024,1024]
    {
        dim3 grid(DM / 128, M / 128);
        sgemm_kernel<<<grid, 256>>>(att, w_o, out, M, DM, DM);
    }
}

// round 4
// speedup vs baseline: 2.0841x; 2.0841x over previous
#include <cuda_runtime.h>
#include <math.h>

#define BB 2
#define SS 2048
#define DM 1024
#define NH 16
#define DK 64
#define WIN 512

// Scratch (no cudaMalloc allowed): qkv = 2*2048*3072 f32 (48MB), attn out = 16MB
__device__ float g_qkv[BB * SS * 3 * DM];
__device__ float g_att[BB * SS * DM];

// ---------------------------------------------------------------------------
// SGEMM: C[M,N] = A[M,K] @ B[K,N], row-major, fp32. (unchanged from R2)
// ---------------------------------------------------------------------------
__global__ __launch_bounds__(256) void sgemm_kernel(
    const float* __restrict__ A, const float* __restrict__ B,
    float* __restrict__ C, int M, int N, int K)
{
    __shared__ float As[8][128];
    __shared__ float Bs[8][128];

    const int tid = threadIdx.x;
    const int tx = tid & 15;
    const int ty = tid >> 4;
    const int m0 = blockIdx.y * 128;
    const int n0 = blockIdx.x * 128;

    float acc[8][8];
#pragma unroll
    for (int i = 0; i < 8; i++)
#pragma unroll
        for (int j = 0; j < 8; j++) acc[i][j] = 0.f;

    const int arow = tid >> 1;
    const int acol = (tid & 1) * 4;
    const int brow = tid >> 5;
    const int bcol = (tid & 31) * 4;

    for (int k0 = 0; k0 < K; k0 += 8) {
        float4 av = *(const float4*)(A + (size_t)(m0 + arow) * K + k0 + acol);
        As[acol + 0][arow] = av.x;
        As[acol + 1][arow] = av.y;
        As[acol + 2][arow] = av.z;
        As[acol + 3][arow] = av.w;
        float4 bv = *(const float4*)(B + (size_t)(k0 + brow) * N + n0 + bcol);
        *(float4*)&Bs[brow][bcol] = bv;
        __syncthreads();

#pragma unroll
        for (int kk = 0; kk < 8; kk++) {
            float a[8], b[8];
            ((float4*)a)[0] = *(const float4*)&As[kk][ty * 8];
            ((float4*)a)[1] = *(const float4*)&As[kk][ty * 8 + 4];
            ((float4*)b)[0] = *(const float4*)&Bs[kk][tx * 8];
            ((float4*)b)[1] = *(const float4*)&Bs[kk][tx * 8 + 4];
#pragma unroll
            for (int i = 0; i < 8; i++)
#pragma unroll
                for (int j = 0; j < 8; j++) acc[i][j] += a[i] * b[j];
        }
        __syncthreads();
    }

#pragma unroll
    for (int i = 0; i < 8; i++) {
        int m = m0 + ty * 8 + i;
        float4* cp = (float4*)(C + (size_t)m * N + n0 + tx * 8);
        cp[0] = make_float4(acc[i][0], acc[i][1], acc[i][2], acc[i][3]);
        cp[1] = make_float4(acc[i][4], acc[i][5], acc[i][6], acc[i][7]);
    }
}

// ---------------------------------------------------------------------------
// RoPE in-place on Q and K slices of g_qkv. (unchanged from R2)
// ---------------------------------------------------------------------------
__global__ void rope_kernel(float* __restrict__ qkv)
{
    int idx = blockIdx.x * blockDim.x + threadIdx.x;
    if (idx >= BB * SS * NH * (DK / 2)) return;
    int i = idx & 31;
    int h = (idx >> 5) & (NH - 1);
    int s = (idx >> 9) & (SS - 1);
    int b = idx >> 20;

    float invf = (float)exp(-(double)i / 32.0 * log(10000.0));
    float ang = (float)s * invf;
    float sn, cs;
    sincosf(ang, &sn, &cs);

    size_t base = ((size_t)(b * SS + s)) * (3 * DM) + h * DK + 2 * i;
    float qe = qkv[base], qo = qkv[base + 1];
    qkv[base]     = qe * cs - qo * sn;
    qkv[base + 1] = qo * cs + qe * sn;
    float ke = qkv[base + DM], ko = qkv[base + DM + 1];
    qkv[base + DM]     = ke * cs - ko * sn;
    qkv[base + DM + 1] = ko * cs + ke * sn;
}

// ---------------------------------------------------------------------------
// Tiled sliding-window attention.
// One CTA per (b, h, 64-query tile). 256 threads, 4x4 register micro-tiles.
// Pass 1: S = Q K^T tile-by-tile into a 64x577 SMEM score array (masked).
// Softmax: exact two-pass, quad-shuffle row reductions.
// Pass 2: O = P V streaming V tiles through SMEM.
// SMEM: Qt[64][68] + KV[64][68] + Sc[64][577] + linv[64] = 178.5 KB dynamic.
// ---------------------------------------------------------------------------
#define TQ 64
#define QPAD 68
#define SCSTRIDE 577   /* 577 % 32 == 1 -> conflict-free column access */

__global__ __launch_bounds__(256) void fattn_kernel(
    const float* __restrict__ qkv, float* __restrict__ out)
{
    extern __shared__ float sm[];
    float* Qt   = sm;                       // [64][QPAD]  (transposed, pre-scaled)
    float* KV   = sm + 64 * QPAD;           // [64][QPAD]  (Kt in pass1, Vs in pass2)
    float* Sc   = sm + 2 * 64 * QPAD;       // [64][SCSTRIDE]
    float* linv = Sc + 64 * SCSTRIDE;       // [64]

    const int qt = blockIdx.x & 31;
    const int h  = (blockIdx.x >> 5) & (NH - 1);
    const int b  = blockIdx.x >> 9;
    const int q0 = qt * TQ;
    const int tid = threadIdx.x;
    const int tx = tid & 15;
    const int ty = tid >> 4;

    const int jbase = (q0 - WIN > 0) ? (q0 - WIN) : 0;
    const int nkt = (q0 + TQ - jbase) >> 6;          // 1..9 key tiles
    const int ncols = q0 + TQ - jbase;               // <= 576

    // --- Load Q tile (transposed, * 1/sqrt(DK)) ---
    {
        const float* Qg = qkv + ((size_t)(b * SS + q0)) * (3 * DM) + h * DK;
        for (int idx = tid; idx < 64 * 16; idx += 256) {
            int r = idx >> 4, d0 = (idx & 15) << 2;
            float4 v = *(const float4*)(Qg + (size_t)r * (3 * DM) + d0);
            Qt[(d0 + 0) * QPAD + r] = v.x * 0.125f;
            Qt[(d0 + 1) * QPAD + r] = v.y * 0.125f;
            Qt[(d0 + 2) * QPAD + r] = v.z * 0.125f;
            Qt[(d0 + 3) * QPAD + r] = v.w * 0.125f;
        }
    }

    // --- Pass 1: scores ---
    for (int kt = 0; kt < nkt; kt++) {
        const int j0k = jbase + kt * 64;
        __syncthreads();
        const float* Kg = qkv + ((size_t)(b * SS + j0k)) * (3 * DM) + DM + h * DK;
        for (int idx = tid; idx < 64 * 16; idx += 256) {
            int r = idx >> 4, d0 = (idx & 15) << 2;
            float4 v = *(const float4*)(Kg + (size_t)r * (3 * DM) + d0);
            KV[(d0 + 0) * QPAD + r] = v.x;
            KV[(d0 + 1) * QPAD + r] = v.y;
            KV[(d0 + 2) * QPAD + r] = v.z;
            KV[(d0 + 3) * QPAD + r] = v.w;
        }
        __syncthreads();

        float acc[4][4];
#pragma unroll
        for (int i = 0; i < 4; i++)
#pragma unroll
            for (int j = 0; j < 4; j++) acc[i][j] = 0.f;

#pragma unroll 4
        for (int d = 0; d < 64; d++) {
            float4 a = *(const float4*)&Qt[d * QPAD + ty * 4];
            float4 bv = *(const float4*)&KV[d * QPAD + tx * 4];
            float av[4] = {a.x, a.y, a.z, a.w};
            float bb[4] = {bv.x, bv.y, bv.z, bv.w};
#pragma unroll
            for (int i = 0; i < 4; i++)
#pragma unroll
                for (int j = 0; j < 4; j++) acc[i][j] += av[i] * bb[j];
        }

        const int c0 = j0k - jbase;
#pragma unroll
        for (int i = 0; i < 4; i++) {
            const int q = q0 + ty * 4 + i;
#pragma unroll
            for (int j = 0; j < 4; j++) {
                const int jj = j0k + tx * 4 + j;
                bool ok = (jj <= q) && (jj + WIN >= q);
                Sc[(ty * 4 + i) * SCSTRIDE + c0 + tx * 4 + j] =
                    ok ? acc[i][j] : -INFINITY;
            }
        }
    }
    __syncthreads();

    // --- Softmax (4 threads per row, quad shuffle reduce) ---
    {
        const int row = tid >> 2, tr = tid & 3;
        float* srow = Sc + row * SCSTRIDE;
        float m = -INFINITY;
        for (int c = tr; c < ncols; c += 4) m = fmaxf(m, srow[c]);
        m = fmaxf(m, __shfl_xor_sync(0xffffffffu, m, 1));
        m = fmaxf(m, __shfl_xor_sync(0xffffffffu, m, 2));
        float l = 0.f;
        for (int c = tr; c < ncols; c += 4) {
            float e = expf(srow[c] - m);
            srow[c] = e;
            l += e;
        }
        l += __shfl_xor_sync(0xffffffffu, l, 1);
        l += __shfl_xor_sync(0xffffffffu, l, 2);
        if (tr == 0) linv[row] = 1.f / l;
    }

    // --- Pass 2: O = P @ V ---
    float o[4][4];
#pragma unroll
    for (int i = 0; i < 4; i++)
#pragma unroll
        for (int j = 0; j < 4; j++) o[i][j] = 0.f;

    for (int kt = 0; kt < nkt; kt++) {
        const int j0k = jbase + kt * 64;
        __syncthreads();
        const float* Vg = qkv + ((size_t)(b * SS + j0k)) * (3 * DM) + 2 * DM + h * DK;
        for (int idx = tid; idx < 64 * 16; idx += 256) {
            int r = idx >> 4, d0 = (idx & 15) << 2;
            float4 v = *(const float4*)(Vg + (size_t)r * (3 * DM) + d0);
            *(float4*)&KV[r * QPAD + d0] = v;
        }
        __syncthreads();

        const int c0 = kt * 64;
#pragma unroll 4
        for (int j = 0; j < 64; j++) {
            float4 v = *(const float4*)&KV[j * QPAD + tx * 4];
            float p0 = Sc[(ty * 4 + 0) * SCSTRIDE + c0 + j];
            float p1 = Sc[(ty * 4 + 1) * SCSTRIDE + c0 + j];
            float p2 = Sc[(ty * 4 + 2) * SCSTRIDE + c0 + j];
            float p3 = Sc[(ty * 4 + 3) * SCSTRIDE + c0 + j];
            o[0][0] += p0 * v.x; o[0][1] += p0 * v.y; o[0][2] += p0 * v.z; o[0][3] += p0 * v.w;
            o[1][0] += p1 * v.x; o[1][1] += p1 * v.y; o[1][2] += p1 * v.z; o[1][3] += p1 * v.w;
            o[2][0] += p2 * v.x; o[2][1] += p2 * v.y; o[2][2] += p2 * v.z; o[2][3] += p2 * v.w;
            o[3][0] += p3 * v.x; o[3][1] += p3 * v.y; o[3][2] += p3 * v.z; o[3][3] += p3 * v.w;
        }
    }

    // --- Normalize + write ---
#pragma unroll
    for (int i = 0; i < 4; i++) {
        const int r = ty * 4 + i;
        const float s = linv[r];
        float4 res = make_float4(o[i][0] * s, o[i][1] * s, o[i][2] * s, o[i][3] * s);
        *(float4*)(out + ((size_t)(b * SS + q0 + r)) * DM + h * DK + tx * 4) = res;
    }
}

// ---------------------------------------------------------------------------
extern "C" void kernel_launch(void* const* d_in, const int* in_sizes, int n_in,
                              void* d_out, int out_size)
{
    const float* x     = (const float*)d_in[0];   // [2,2048,1024]
    const float* w_qkv = (const float*)d_in[1];   // [1024,3072]
    const float* w_o   = (const float*)d_in[2];   // [1024,1024]
    float* out = (float*)d_out;                   // [2,2048,1024]

    float* qkv = nullptr;
    float* att = nullptr;
    cudaGetSymbolAddress((void**)&qkv, g_qkv);
    cudaGetSymbolAddress((void**)&att, g_att);

    const int M = BB * SS;  // 4096

    // 1) QKV projection: [4096,1024] @ [1024,3072]
    {
        dim3 grid(3 * DM / 128, M / 128);
        sgemm_kernel<<<grid, 256>>>(x, w_qkv, qkv, M, 3 * DM, DM);
    }
    // 2) RoPE on Q and K slices (in place)
    {
        int total = BB * SS * NH * (DK / 2);
        rope_kernel<<<(total + 255) / 256, 256>>>(qkv);
    }
    // 3) Tiled sliding-window attention
    {
        const int smem_bytes = (2 * 64 * QPAD + 64 * SCSTRIDE + 64) * sizeof(float);
        static bool attr_set = false;
        if (!attr_set) {
            cudaFuncSetAttribute(fattn_kernel,
                                 cudaFuncAttributeMaxDynamicSharedMemorySize,
                                 smem_bytes);
            attr_set = true;
        }
        fattn_kernel<<<BB * NH * 32, 256, smem_bytes>>>(qkv, att);
    }
    // 4) Output projection: [4096,1024] @ [1024,1024]
    {
        dim3 grid(DM / 128, M / 128);
        sgemm_kernel<<<grid, 256>>>(att, w_o, out, M, DM, DM);
    }
}

// round 5
// speedup vs baseline: 2.0867x; 1.0012x over previous
#include <cuda_runtime.h>
#include <math.h>

#define BB 2
#define SS 2048
#define DM 1024
#define NH 16
#define DK 64
#define WIN 512

// Scratch (no cudaMalloc allowed): qkv = 2*2048*3072 f32 (48MB), attn out = 16MB
__device__ float g_qkv[BB * SS * 3 * DM];
__device__ float g_att[BB * SS * DM];

// ---------------------------------------------------------------------------
// SGEMM: C[M,N] = A[M,K] @ B[K,N], row-major, fp32. (unchanged from R2)
// ---------------------------------------------------------------------------
__global__ __launch_bounds__(256) void sgemm_kernel(
    const float* __restrict__ A, const float* __restrict__ B,
    float* __restrict__ C, int M, int N, int K)
{
    __shared__ float As[8][128];
    __shared__ float Bs[8][128];

    const int tid = threadIdx.x;
    const int tx = tid & 15;
    const int ty = tid >> 4;
    const int m0 = blockIdx.y * 128;
    const int n0 = blockIdx.x * 128;

    float acc[8][8];
#pragma unroll
    for (int i = 0; i < 8; i++)
#pragma unroll
        for (int j = 0; j < 8; j++) acc[i][j] = 0.f;

    const int arow = tid >> 1;
    const int acol = (tid & 1) * 4;
    const int brow = tid >> 5;
    const int bcol = (tid & 31) * 4;

    for (int k0 = 0; k0 < K; k0 += 8) {
        float4 av = *(const float4*)(A + (size_t)(m0 + arow) * K + k0 + acol);
        As[acol + 0][arow] = av.x;
        As[acol + 1][arow] = av.y;
        As[acol + 2][arow] = av.z;
        As[acol + 3][arow] = av.w;
        float4 bv = *(const float4*)(B + (size_t)(k0 + brow) * N + n0 + bcol);
        *(float4*)&Bs[brow][bcol] = bv;
        __syncthreads();

#pragma unroll
        for (int kk = 0; kk < 8; kk++) {
            float a[8], b[8];
            ((float4*)a)[0] = *(const float4*)&As[kk][ty * 8];
            ((float4*)a)[1] = *(const float4*)&As[kk][ty * 8 + 4];
            ((float4*)b)[0] = *(const float4*)&Bs[kk][tx * 8];
            ((float4*)b)[1] = *(const float4*)&Bs[kk][tx * 8 + 4];
#pragma unroll
            for (int i = 0; i < 8; i++)
#pragma unroll
                for (int j = 0; j < 8; j++) acc[i][j] += a[i] * b[j];
        }
        __syncthreads();
    }

#pragma unroll
    for (int i = 0; i < 8; i++) {
        int m = m0 + ty * 8 + i;
        float4* cp = (float4*)(C + (size_t)m * N + n0 + tx * 8);
        cp[0] = make_float4(acc[i][0], acc[i][1], acc[i][2], acc[i][3]);
        cp[1] = make_float4(acc[i][4], acc[i][5], acc[i][6], acc[i][7]);
    }
}

// ---------------------------------------------------------------------------
// RoPE in-place on Q and K slices of g_qkv. (unchanged from R2)
// ---------------------------------------------------------------------------
__global__ void rope_kernel(float* __restrict__ qkv)
{
    int idx = blockIdx.x * blockDim.x + threadIdx.x;
    if (idx >= BB * SS * NH * (DK / 2)) return;
    int i = idx & 31;
    int h = (idx >> 5) & (NH - 1);
    int s = (idx >> 9) & (SS - 1);
    int b = idx >> 20;

    float invf = (float)exp(-(double)i / 32.0 * log(10000.0));
    float ang = (float)s * invf;
    float sn, cs;
    sincosf(ang, &sn, &cs);

    size_t base = ((size_t)(b * SS + s)) * (3 * DM) + h * DK + 2 * i;
    float qe = qkv[base], qo = qkv[base + 1];
    qkv[base]     = qe * cs - qo * sn;
    qkv[base + 1] = qo * cs + qe * sn;
    float ke = qkv[base + DM], ko = qkv[base + DM + 1];
    qkv[base + DM]     = ke * cs - ko * sn;
    qkv[base + DM + 1] = ko * cs + ke * sn;
}

// ---------------------------------------------------------------------------
// Tiled sliding-window attention.
// One CTA per (b, h, 64-query tile). 256 threads, 4x4 register micro-tiles.
// Pass 1: S = Q K^T tile-by-tile into a 64x577 SMEM score array (masked).
// Softmax: exact two-pass, quad-shuffle row reductions.
// Pass 2: O = P V streaming V tiles through SMEM.
// SMEM: Qt[64][68] + KV[64][68] + Sc[64][577] + linv[64] = 178.5 KB dynamic.
// ---------------------------------------------------------------------------
#define TQ 64
#define QPAD 68
#define SCSTRIDE 577   /* 577 % 32 == 1 -> conflict-free column access */

__global__ __launch_bounds__(256) void fattn_kernel(
    const float* __restrict__ qkv, float* __restrict__ out)
{
    extern __shared__ float sm[];
    float* Qt   = sm;                       // [64][QPAD]  (transposed, pre-scaled)
    float* KV   = sm + 64 * QPAD;           // [64][QPAD]  (Kt in pass1, Vs in pass2)
    float* Sc   = sm + 2 * 64 * QPAD;       // [64][SCSTRIDE]
    float* linv = Sc + 64 * SCSTRIDE;       // [64]

    const int qt = blockIdx.x & 31;
    const int h  = (blockIdx.x >> 5) & (NH - 1);
    const int b  = blockIdx.x >> 9;
    const int q0 = qt * TQ;
    const int tid = threadIdx.x;
    const int tx = tid & 15;
    const int ty = tid >> 4;

    const int jbase = (q0 - WIN > 0) ? (q0 - WIN) : 0;
    const int nkt = (q0 + TQ - jbase) >> 6;          // 1..9 key tiles
    const int ncols = q0 + TQ - jbase;               // <= 576

    // --- Load Q tile (transposed, * 1/sqrt(DK)) ---
    {
        const float* Qg = qkv + ((size_t)(b * SS + q0)) * (3 * DM) + h * DK;
        for (int idx = tid; idx < 64 * 16; idx += 256) {
            int r = idx >> 4, d0 = (idx & 15) << 2;
            float4 v = *(const float4*)(Qg + (size_t)r * (3 * DM) + d0);
            Qt[(d0 + 0) * QPAD + r] = v.x * 0.125f;
            Qt[(d0 + 1) * QPAD + r] = v.y * 0.125f;
            Qt[(d0 + 2) * QPAD + r] = v.z * 0.125f;
            Qt[(d0 + 3) * QPAD + r] = v.w * 0.125f;
        }
    }

    // --- Pass 1: scores ---
    for (int kt = 0; kt < nkt; kt++) {
        const int j0k = jbase + kt * 64;
        __syncthreads();
        const float* Kg = qkv + ((size_t)(b * SS + j0k)) * (3 * DM) + DM + h * DK;
        for (int idx = tid; idx < 64 * 16; idx += 256) {
            int r = idx >> 4, d0 = (idx & 15) << 2;
            float4 v = *(const float4*)(Kg + (size_t)r * (3 * DM) + d0);
            KV[(d0 + 0) * QPAD + r] = v.x;
            KV[(d0 + 1) * QPAD + r] = v.y;
            KV[(d0 + 2) * QPAD + r] = v.z;
            KV[(d0 + 3) * QPAD + r] = v.w;
        }
        __syncthreads();

        float acc[4][4];
#pragma unroll
        for (int i = 0; i < 4; i++)
#pragma unroll
            for (int j = 0; j < 4; j++) acc[i][j] = 0.f;

#pragma unroll 4
        for (int d = 0; d < 64; d++) {
            float4 a = *(const float4*)&Qt[d * QPAD + ty * 4];
            float4 bv = *(const float4*)&KV[d * QPAD + tx * 4];
            float av[4] = {a.x, a.y, a.z, a.w};
            float bb[4] = {bv.x, bv.y, bv.z, bv.w};
#pragma unroll
            for (int i = 0; i < 4; i++)
#pragma unroll
                for (int j = 0; j < 4; j++) acc[i][j] += av[i] * bb[j];
        }

        const int c0 = j0k - jbase;
#pragma unroll
        for (int i = 0; i < 4; i++) {
            const int q = q0 + ty * 4 + i;
#pragma unroll
            for (int j = 0; j < 4; j++) {
                const int jj = j0k + tx * 4 + j;
                bool ok = (jj <= q) && (jj + WIN >= q);
                Sc[(ty * 4 + i) * SCSTRIDE + c0 + tx * 4 + j] =
                    ok ? acc[i][j] : -INFINITY;
            }
        }
    }
    __syncthreads();

    // --- Softmax (4 threads per row, quad shuffle reduce) ---
    {
        const int row = tid >> 2, tr = tid & 3;
        float* srow = Sc + row * SCSTRIDE;
        float m = -INFINITY;
        for (int c = tr; c < ncols; c += 4) m = fmaxf(m, srow[c]);
        m = fmaxf(m, __shfl_xor_sync(0xffffffffu, m, 1));
        m = fmaxf(m, __shfl_xor_sync(0xffffffffu, m, 2));
        float l = 0.f;
        for (int c = tr; c < ncols; c += 4) {
            float e = expf(srow[c] - m);
            srow[c] = e;
            l += e;
        }
        l += __shfl_xor_sync(0xffffffffu, l, 1);
        l += __shfl_xor_sync(0xffffffffu, l, 2);
        if (tr == 0) linv[row] = 1.f / l;
    }

    // --- Pass 2: O = P @ V ---
    float o[4][4];
#pragma unroll
    for (int i = 0; i < 4; i++)
#pragma unroll
        for (int j = 0; j < 4; j++) o[i][j] = 0.f;

    for (int kt = 0; kt < nkt; kt++) {
        const int j0k = jbase + kt * 64;
        __syncthreads();
        const float* Vg = qkv + ((size_t)(b * SS + j0k)) * (3 * DM) + 2 * DM + h * DK;
        for (int idx = tid; idx < 64 * 16; idx += 256) {
            int r = idx >> 4, d0 = (idx & 15) << 2;
            float4 v = *(const float4*)(Vg + (size_t)r * (3 * DM) + d0);
            *(float4*)&KV[r * QPAD + d0] = v;
        }
        __syncthreads();

        const int c0 = kt * 64;
#pragma unroll 4
        for (int j = 0; j < 64; j++) {
            float4 v = *(const float4*)&KV[j * QPAD + tx * 4];
            float p0 = Sc[(ty * 4 + 0) * SCSTRIDE + c0 + j];
            float p1 = Sc[(ty * 4 + 1) * SCSTRIDE + c0 + j];
            float p2 = Sc[(ty * 4 + 2) * SCSTRIDE + c0 + j];
            float p3 = Sc[(ty * 4 + 3) * SCSTRIDE + c0 + j];
            o[0][0] += p0 * v.x; o[0][1] += p0 * v.y; o[0][2] += p0 * v.z; o[0][3] += p0 * v.w;
            o[1][0] += p1 * v.x; o[1][1] += p1 * v.y; o[1][2] += p1 * v.z; o[1][3] += p1 * v.w;
            o[2][0] += p2 * v.x; o[2][1] += p2 * v.y; o[2][2] += p2 * v.z; o[2][3] += p2 * v.w;
            o[3][0] += p3 * v.x; o[3][1] += p3 * v.y; o[3][2] += p3 * v.z; o[3][3] += p3 * v.w;
        }
    }

    // --- Normalize + write ---
#pragma unroll
    for (int i = 0; i < 4; i++) {
        const int r = ty * 4 + i;
        const float s = linv[r];
        float4 res = make_float4(o[i][0] * s, o[i][1] * s, o[i][2] * s, o[i][3] * s);
        *(float4*)(out + ((size_t)(b * SS + q0 + r)) * DM + h * DK + tx * 4) = res;
    }
}

// ---------------------------------------------------------------------------
extern "C" void kernel_launch(void* const* d_in, const int* in_sizes, int n_in,
                              void* d_out, int out_size)
{
    const float* x     = (const float*)d_in[0];   // [2,2048,1024]
    const float* w_qkv = (const float*)d_in[1];   // [1024,3072]
    const float* w_o   = (const float*)d_in[2];   // [1024,1024]
    float* out = (float*)d_out;                   // [2,2048,1024]

    float* qkv = nullptr;
    float* att = nullptr;
    cudaGetSymbolAddress((void**)&qkv, g_qkv);
    cudaGetSymbolAddress((void**)&att, g_att);

    const int M = BB * SS;  // 4096

    // 1) QKV projection: [4096,1024] @ [1024,3072]
    {
        dim3 grid(3 * DM / 128, M / 128);
        sgemm_kernel<<<grid, 256>>>(x, w_qkv, qkv, M, 3 * DM, DM);
    }
    // 2) RoPE on Q and K slices (in place)
    {
        int total = BB * SS * NH * (DK / 2);
        rope_kernel<<<(total + 255) / 256, 256>>>(qkv);
    }
    // 3) Tiled sliding-window attention
    {
        const int smem_bytes = (2 * 64 * QPAD + 64 * SCSTRIDE + 64) * sizeof(float);
        static bool attr_set = false;
        if (!attr_set) {
            cudaFuncSetAttribute(fattn_kernel,
                                 cudaFuncAttributeMaxDynamicSharedMemorySize,
                                 smem_bytes);
            attr_set = true;
        }
        fattn_kernel<<<BB * NH * 32, 256, smem_bytes>>>(qkv, att);
    }
    // 4) Output projection: [4096,1024] @ [1024,1024]
    {
        dim3 grid(DM / 128, M / 128);
        sgemm_kernel<<<grid, 256>>>(att, w_o, out, M, DM, DM);
    }
}

// round 6
// speedup vs baseline: 2.0909x; 1.0020x over previous
#include <cuda_runtime.h>
#include <math.h>

#define BB 2
#define SS 2048
#define DM 1024
#define NH 16
#define DK 64
#define WIN 512

// Scratch (no cudaMalloc allowed): qkv = 2*2048*3072 f32 (48MB), attn out = 16MB
__device__ float g_qkv[BB * SS * 3 * DM];
__device__ float g_att[BB * SS * DM];

// ---------------------------------------------------------------------------
// SGEMM: C[M,N] = A[M,K] @ B[K,N], row-major, fp32. (unchanged from R2)
// ---------------------------------------------------------------------------
__global__ __launch_bounds__(256) void sgemm_kernel(
    const float* __restrict__ A, const float* __restrict__ B,
    float* __restrict__ C, int M, int N, int K)
{
    __shared__ float As[8][128];
    __shared__ float Bs[8][128];

    const int tid = threadIdx.x;
    const int tx = tid & 15;
    const int ty = tid >> 4;
    const int m0 = blockIdx.y * 128;
    const int n0 = blockIdx.x * 128;

    float acc[8][8];
#pragma unroll
    for (int i = 0; i < 8; i++)
#pragma unroll
        for (int j = 0; j < 8; j++) acc[i][j] = 0.f;

    const int arow = tid >> 1;
    const int acol = (tid & 1) * 4;
    const int brow = tid >> 5;
    const int bcol = (tid & 31) * 4;

    for (int k0 = 0; k0 < K; k0 += 8) {
        float4 av = *(const float4*)(A + (size_t)(m0 + arow) * K + k0 + acol);
        As[acol + 0][arow] = av.x;
        As[acol + 1][arow] = av.y;
        As[acol + 2][arow] = av.z;
        As[acol + 3][arow] = av.w;
        float4 bv = *(const float4*)(B + (size_t)(k0 + brow) * N + n0 + bcol);
        *(float4*)&Bs[brow][bcol] = bv;
        __syncthreads();

#pragma unroll
        for (int kk = 0; kk < 8; kk++) {
            float a[8], b[8];
            ((float4*)a)[0] = *(const float4*)&As[kk][ty * 8];
            ((float4*)a)[1] = *(const float4*)&As[kk][ty * 8 + 4];
            ((float4*)b)[0] = *(const float4*)&Bs[kk][tx * 8];
            ((float4*)b)[1] = *(const float4*)&Bs[kk][tx * 8 + 4];
#pragma unroll
            for (int i = 0; i < 8; i++)
#pragma unroll
                for (int j = 0; j < 8; j++) acc[i][j] += a[i] * b[j];
        }
        __syncthreads();
    }

#pragma unroll
    for (int i = 0; i < 8; i++) {
        int m = m0 + ty * 8 + i;
        float4* cp = (float4*)(C + (size_t)m * N + n0 + tx * 8);
        cp[0] = make_float4(acc[i][0], acc[i][1], acc[i][2], acc[i][3]);
        cp[1] = make_float4(acc[i][4], acc[i][5], acc[i][6], acc[i][7]);
    }
}

// ---------------------------------------------------------------------------
// RoPE in-place on Q and K slices of g_qkv. (unchanged from R2)
// ---------------------------------------------------------------------------
__global__ void rope_kernel(float* __restrict__ qkv)
{
    int idx = blockIdx.x * blockDim.x + threadIdx.x;
    if (idx >= BB * SS * NH * (DK / 2)) return;
    int i = idx & 31;
    int h = (idx >> 5) & (NH - 1);
    int s = (idx >> 9) & (SS - 1);
    int b = idx >> 20;

    float invf = (float)exp(-(double)i / 32.0 * log(10000.0));
    float ang = (float)s * invf;
    float sn, cs;
    sincosf(ang, &sn, &cs);

    size_t base = ((size_t)(b * SS + s)) * (3 * DM) + h * DK + 2 * i;
    float qe = qkv[base], qo = qkv[base + 1];
    qkv[base]     = qe * cs - qo * sn;
    qkv[base + 1] = qo * cs + qe * sn;
    float ke = qkv[base + DM], ko = qkv[base + DM + 1];
    qkv[base + DM]     = ke * cs - ko * sn;
    qkv[base + DM + 1] = ko * cs + ke * sn;
}

// ---------------------------------------------------------------------------
// Tiled sliding-window attention.
// One CTA per (b, h, 64-query tile). 256 threads, 4x4 register micro-tiles.
// Pass 1: S = Q K^T tile-by-tile into a 64x577 SMEM score array (masked).
// Softmax: exact two-pass, quad-shuffle row reductions.
// Pass 2: O = P V streaming V tiles through SMEM.
// SMEM: Qt[64][68] + KV[64][68] + Sc[64][577] + linv[64] = 178.5 KB dynamic.
// ---------------------------------------------------------------------------
#define TQ 64
#define QPAD 68
#define SCSTRIDE 577   /* 577 % 32 == 1 -> conflict-free column access */

__global__ __launch_bounds__(256) void fattn_kernel(
    const float* __restrict__ qkv, float* __restrict__ out)
{
    extern __shared__ float sm[];
    float* Qt   = sm;                       // [64][QPAD]  (transposed, pre-scaled)
    float* KV   = sm + 64 * QPAD;           // [64][QPAD]  (Kt in pass1, Vs in pass2)
    float* Sc   = sm + 2 * 64 * QPAD;       // [64][SCSTRIDE]
    float* linv = Sc + 64 * SCSTRIDE;       // [64]

    const int qt = blockIdx.x & 31;
    const int h  = (blockIdx.x >> 5) & (NH - 1);
    const int b  = blockIdx.x >> 9;
    const int q0 = qt * TQ;
    const int tid = threadIdx.x;
    const int tx = tid & 15;
    const int ty = tid >> 4;

    const int jbase = (q0 - WIN > 0) ? (q0 - WIN) : 0;
    const int nkt = (q0 + TQ - jbase) >> 6;          // 1..9 key tiles
    const int ncols = q0 + TQ - jbase;               // <= 576

    // --- Load Q tile (transposed, * 1/sqrt(DK)) ---
    {
        const float* Qg = qkv + ((size_t)(b * SS + q0)) * (3 * DM) + h * DK;
        for (int idx = tid; idx < 64 * 16; idx += 256) {
            int r = idx >> 4, d0 = (idx & 15) << 2;
            float4 v = *(const float4*)(Qg + (size_t)r * (3 * DM) + d0);
            Qt[(d0 + 0) * QPAD + r] = v.x * 0.125f;
            Qt[(d0 + 1) * QPAD + r] = v.y * 0.125f;
            Qt[(d0 + 2) * QPAD + r] = v.z * 0.125f;
            Qt[(d0 + 3) * QPAD + r] = v.w * 0.125f;
        }
    }

    // --- Pass 1: scores ---
    for (int kt = 0; kt < nkt; kt++) {
        const int j0k = jbase + kt * 64;
        __syncthreads();
        const float* Kg = qkv + ((size_t)(b * SS + j0k)) * (3 * DM) + DM + h * DK;
        for (int idx = tid; idx < 64 * 16; idx += 256) {
            int r = idx >> 4, d0 = (idx & 15) << 2;
            float4 v = *(const float4*)(Kg + (size_t)r * (3 * DM) + d0);
            KV[(d0 + 0) * QPAD + r] = v.x;
            KV[(d0 + 1) * QPAD + r] = v.y;
            KV[(d0 + 2) * QPAD + r] = v.z;
            KV[(d0 + 3) * QPAD + r] = v.w;
        }
        __syncthreads();

        float acc[4][4];
#pragma unroll
        for (int i = 0; i < 4; i++)
#pragma unroll
            for (int j = 0; j < 4; j++) acc[i][j] = 0.f;

#pragma unroll 4
        for (int d = 0; d < 64; d++) {
            float4 a = *(const float4*)&Qt[d * QPAD + ty * 4];
            float4 bv = *(const float4*)&KV[d * QPAD + tx * 4];
            float av[4] = {a.x, a.y, a.z, a.w};
            float bb[4] = {bv.x, bv.y, bv.z, bv.w};
#pragma unroll
            for (int i = 0; i < 4; i++)
#pragma unroll
                for (int j = 0; j < 4; j++) acc[i][j] += av[i] * bb[j];
        }

        const int c0 = j0k - jbase;
#pragma unroll
        for (int i = 0; i < 4; i++) {
            const int q = q0 + ty * 4 + i;
#pragma unroll
            for (int j = 0; j < 4; j++) {
                const int jj = j0k + tx * 4 + j;
                bool ok = (jj <= q) && (jj + WIN >= q);
                Sc[(ty * 4 + i) * SCSTRIDE + c0 + tx * 4 + j] =
                    ok ? acc[i][j] : -INFINITY;
            }
        }
    }
    __syncthreads();

    // --- Softmax (4 threads per row, quad shuffle reduce) ---
    {
        const int row = tid >> 2, tr = tid & 3;
        float* srow = Sc + row * SCSTRIDE;
        float m = -INFINITY;
        for (int c = tr; c < ncols; c += 4) m = fmaxf(m, srow[c]);
        m = fmaxf(m, __shfl_xor_sync(0xffffffffu, m, 1));
        m = fmaxf(m, __shfl_xor_sync(0xffffffffu, m, 2));
        float l = 0.f;
        for (int c = tr; c < ncols; c += 4) {
            float e = expf(srow[c] - m);
            srow[c] = e;
            l += e;
        }
        l += __shfl_xor_sync(0xffffffffu, l, 1);
        l += __shfl_xor_sync(0xffffffffu, l, 2);
        if (tr == 0) linv[row] = 1.f / l;
    }

    // --- Pass 2: O = P @ V ---
    float o[4][4];
#pragma unroll
    for (int i = 0; i < 4; i++)
#pragma unroll
        for (int j = 0; j < 4; j++) o[i][j] = 0.f;

    for (int kt = 0; kt < nkt; kt++) {
        const int j0k = jbase + kt * 64;
        __syncthreads();
        const float* Vg = qkv + ((size_t)(b * SS + j0k)) * (3 * DM) + 2 * DM + h * DK;
        for (int idx = tid; idx < 64 * 16; idx += 256) {
            int r = idx >> 4, d0 = (idx & 15) << 2;
            float4 v = *(const float4*)(Vg + (size_t)r * (3 * DM) + d0);
            *(float4*)&KV[r * QPAD + d0] = v;
        }
        __syncthreads();

        const int c0 = kt * 64;
#pragma unroll 4
        for (int j = 0; j < 64; j++) {
            float4 v = *(const float4*)&KV[j * QPAD + tx * 4];
            float p0 = Sc[(ty * 4 + 0) * SCSTRIDE + c0 + j];
            float p1 = Sc[(ty * 4 + 1) * SCSTRIDE + c0 + j];
            float p2 = Sc[(ty * 4 + 2) * SCSTRIDE + c0 + j];
            float p3 = Sc[(ty * 4 + 3) * SCSTRIDE + c0 + j];
            o[0][0] += p0 * v.x; o[0][1] += p0 * v.y; o[0][2] += p0 * v.z; o[0][3] += p0 * v.w;
            o[1][0] += p1 * v.x; o[1][1] += p1 * v.y; o[1][2] += p1 * v.z; o[1][3] += p1 * v.w;
            o[2][0] += p2 * v.x; o[2][1] += p2 * v.y; o[2][2] += p2 * v.z; o[2][3] += p2 * v.w;
            o[3][0] += p3 * v.x; o[3][1] += p3 * v.y; o[3][2] += p3 * v.z; o[3][3] += p3 * v.w;
        }
    }

    // --- Normalize + write ---
#pragma unroll
    for (int i = 0; i < 4; i++) {
        const int r = ty * 4 + i;
        const float s = linv[r];
        float4 res = make_float4(o[i][0] * s, o[i][1] * s, o[i][2] * s, o[i][3] * s);
        *(float4*)(out + ((size_t)(b * SS + q0 + r)) * DM + h * DK + tx * 4) = res;
    }
}

// ---------------------------------------------------------------------------
extern "C" void kernel_launch(void* const* d_in, const int* in_sizes, int n_in,
                              void* d_out, int out_size)
{
    const float* x     = (const float*)d_in[0];   // [2,2048,1024]
    const float* w_qkv = (const float*)d_in[1];   // [1024,3072]
    const float* w_o   = (const float*)d_in[2];   // [1024,1024]
    float* out = (float*)d_out;                   // [2,2048,1024]

    float* qkv = nullptr;
    float* att = nullptr;
    cudaGetSymbolAddress((void**)&qkv, g_qkv);
    cudaGetSymbolAddress((void**)&att, g_att);

    const int M = BB * SS;  // 4096

    // 1) QKV projection: [4096,1024] @ [1024,3072]
    {
        dim3 grid(3 * DM / 128, M / 128);
        sgemm_kernel<<<grid, 256>>>(x, w_qkv, qkv, M, 3 * DM, DM);
    }
    // 2) RoPE on Q and K slices (in place)
    {
        int total = BB * SS * NH * (DK / 2);
        rope_kernel<<<(total + 255) / 256, 256>>>(qkv);
    }
    // 3) Tiled sliding-window attention
    {
        const int smem_bytes = (2 * 64 * QPAD + 64 * SCSTRIDE + 64) * sizeof(float);
        static bool attr_set = false;
        if (!attr_set) {
            cudaFuncSetAttribute(fattn_kernel,
                                 cudaFuncAttributeMaxDynamicSharedMemorySize,
                                 smem_bytes);
            attr_set = true;
        }
        fattn_kernel<<<BB * NH * 32, 256, smem_bytes>>>(qkv, att);
    }
    // 4) Output projection: [4096,1024] @ [1024,1024]
    {
        dim3 grid(DM / 128, M / 128);
        sgemm_kernel<<<grid, 256>>>(att, w_o, out, M, DM, DM);
    }
}